// round 17
// baseline (speedup 1.0000x reference)
#include <cuda_runtime.h>
#include <cuda_bf16.h>
#include <cuda_fp16.h>
#include <cstdint>
#include <math.h>

#define EPSN 1e-6f
#define NB 8
#define NM 16384
#define GRIP_OFF (NB*NM*6)
#define AC_OFF   (GRIP_OFF+16)
#define TSP  32
#define ROWB 192                 // bytes per act row (96 fp16)
#define IMG  24576               // act image bytes (128 rows)
#define WOFF 49152               // weight stage (32KB fp16)
#define SMEM_TOTAL 81920

__device__ __align__(16) __half g_W16[5][16384];   // [o][k] row-major fp16
__device__ float g_bias1[NB*128*3];
__device__ float g_s2v1[NB*128];
__device__ float g_grip[NB*2];
__device__ int   g_closest[NB*2];

// ---------------- helpers ----------------
__device__ __forceinline__ uint32_t smem_u32(const void* p){
    uint32_t a; asm("{ .reg .u64 t; cvta.to.shared.u64 t, %1; cvt.u32.u64 %0, t; }" : "=r"(a) : "l"(p)); return a;
}
__device__ __forceinline__ uint32_t pk_hf(float a, float b){
    return (uint32_t)__half_as_ushort(__float2half_rn(a)) |
           ((uint32_t)__half_as_ushort(__float2half_rn(b)) << 16);
}
__device__ __forceinline__ float hl(uint32_t v){ return __half2float(__ushort_as_half((unsigned short)(v & 0xFFFF))); }
__device__ __forceinline__ float hh(uint32_t v){ return __half2float(__ushort_as_half((unsigned short)(v >> 16))); }

__device__ __forceinline__ void mma_f16(float* c, const uint32_t* a, uint32_t b0, uint32_t b1){
    asm("mma.sync.aligned.m16n8k16.row.col.f32.f16.f16.f32 "
        "{%0,%1,%2,%3},{%4,%5,%6,%7},{%8,%9},{%0,%1,%2,%3};"
        : "+f"(c[0]), "+f"(c[1]), "+f"(c[2]), "+f"(c[3])
        : "r"(a[0]), "r"(a[1]), "r"(a[2]), "r"(a[3]), "r"(b0), "r"(b1));
}
__device__ __forceinline__ void ldsm4t(uint32_t& r0, uint32_t& r1, uint32_t& r2, uint32_t& r3, uint32_t addr){
    asm volatile("ldmatrix.sync.aligned.m8n8.x4.trans.shared.b16 {%0,%1,%2,%3}, [%4];"
        : "=r"(r0), "=r"(r1), "=r"(r2), "=r"(r3) : "r"(addr) : "memory");
}
__device__ __forceinline__ void ldsm4(uint32_t* r, uint32_t addr){
    asm volatile("ldmatrix.sync.aligned.m8n8.x4.shared.b16 {%0,%1,%2,%3}, [%4];"
        : "=r"(r[0]), "=r"(r[1]), "=r"(r[2]), "=r"(r[3]) : "r"(addr) : "memory");
}
__device__ __forceinline__ void cp16(void* dst, const void* src){
    unsigned d = smem_u32(dst);
    asm volatile("cp.async.cg.shared.global [%0], [%1], 16;" :: "r"(d), "l"(src));
}
__device__ __forceinline__ void cpcommit(){ asm volatile("cp.async.commit_group;"); }
__device__ __forceinline__ void cpwait0(){ asm volatile("cp.async.wait_group 0;"); }

__device__ __forceinline__ void wred3(float& s0, float& s1, float& s2){
    #pragma unroll
    for (int t = 16; t; t >>= 1){
        s0 += __shfl_xor_sync(0xFFFFFFFFu, s0, t);
        s1 += __shfl_xor_sync(0xFFFFFFFFu, s1, t);
        s2 += __shfl_xor_sync(0xFFFFFFFFu, s2, t);
    }
}

// one GEMM layer: NAT A-tiles (16 rows) x (8 points x 3 d), 2-pass xhi/xlo
template<int NAT>
__device__ __forceinline__ void layer2p(float acc[NAT][3][4],
    uint32_t Ws, uint32_t sbA, int pq, int mrow0, int lane)
{
    #pragma unroll
    for (int at = 0; at < NAT; at++)
        #pragma unroll
        for (int d = 0; d < 3; d++){ acc[at][d][0]=0.f; acc[at][d][1]=0.f; acc[at][d][2]=0.f; acc[at][d][3]=0.f; }

    const int rr = lane & 15, chA = lane >> 4, keyA = lane & 7;
    const int keyB = (rr >> 1) & 3;
    const uint32_t brow = sbA + ((lane >= 16) ? (uint32_t)IMG : 0u) + (uint32_t)rr*ROWB;
    const uint32_t ab0 = Ws + (uint32_t)(mrow0 + rr)*256;
    const uint32_t ab1 = ab0 + 16*256;
    uint32_t coffs[3];
    #pragma unroll
    for (int d = 0; d < 3; d++) coffs[d] = (uint32_t)((d*4 + (pq ^ keyB)) << 4);

    #pragma unroll
    for (int kt = 0; kt < 8; kt++){
        const uint32_t ka = (uint32_t)(((2*kt + chA) ^ keyA) << 4);
        uint32_t a0[4], a1[4];
        ldsm4(a0, ab0 + ka);
        if (NAT == 2) ldsm4(a1, ab1 + ka);
        const uint32_t kb = brow + (uint32_t)kt*16*ROWB;
        #pragma unroll
        for (int d = 0; d < 3; d++){
            uint32_t b0,b1,b2,b3;                 // {b0,b1}=xhi, {b2,b3}=xlo
            ldsm4t(b0,b1,b2,b3, kb + coffs[d]);
            mma_f16(acc[0][d], a0, b0, b1);
            mma_f16(acc[0][d], a0, b2, b3);
            if (NAT == 2){
                mma_f16(acc[1][d], a1, b0, b1);
                mma_f16(acc[1][d], a1, b2, b3);
            }
        }
    }
}

// epilogues: MODE 0 = bias+gate, 1 = LNA, 2 = raw copy
template<int MODE>
__device__ __forceinline__ void epi(float acc[2][3][4], char* sm, int mrow0, int pq,
                                    int qr, int cb, int bbase)
{
    #pragma unroll
    for (int at = 0; at < 2; at++){
        #pragma unroll
        for (int r = 0; r < 2; r++){
            const int o = mrow0 + at*16 + qr + r*8;
            const int keyo = (o >> 1) & 3;
            float b0=0.f, b1=0.f, b2=0.f, sv=0.f;
            if (MODE == 0){
                b0 = g_bias1[(bbase+o)*3+0]; b1 = g_bias1[(bbase+o)*3+1]; b2 = g_bias1[(bbase+o)*3+2];
                sv = g_s2v1[bbase+o];
            }
            uint32_t offd[3];
            #pragma unroll
            for (int d = 0; d < 3; d++)
                offd[d] = (uint32_t)(o*ROWB + ((d*4 + (pq ^ keyo)) << 4) + cb*2);
            float x0 = acc[at][0][2*r], x1 = acc[at][0][2*r+1];
            float y0 = acc[at][1][2*r], y1 = acc[at][1][2*r+1];
            float z0 = acc[at][2][2*r], z1 = acc[at][2][2*r+1];
            float h3[3][2];
            if (MODE == 0){
                float q00=x0+b0, q10=y0+b1, q20=z0+b2;
                float q01=x1+b0, q11=y1+b1, q21=z1+b2;
                float g0 = 1.0f + sv/(sqrtf(q00*q00+q10*q10+q20*q20)+EPSN);
                float g1 = 1.0f + sv/(sqrtf(q01*q01+q11*q11+q21*q21)+EPSN);
                h3[0][0]=q00*g0; h3[1][0]=q10*g0; h3[2][0]=q20*g0;
                h3[0][1]=q01*g1; h3[1][1]=q11*g1; h3[2][1]=q21*g1;
            } else if (MODE == 2){
                h3[0][0]=x0; h3[0][1]=x1; h3[1][0]=y0; h3[1][1]=y1; h3[2][0]=z0; h3[2][1]=z1;
            } else {
                float q[3][2];
                #pragma unroll
                for (int d = 0; d < 3; d++){
                    uint32_t qh = *(uint32_t*)(sm + offd[d]);
                    uint32_t ql = *(uint32_t*)(sm + IMG + offd[d]);
                    q[d][0] = hl(qh)+hl(ql); q[d][1] = hh(qh)+hh(ql);
                }
                float inv0 = 1.0f/(sqrtf(x0*x0+y0*y0+z0*z0)+EPSN);
                float mf0  = fminf((q[0][0]*x0+q[1][0]*y0+q[2][0]*z0)*inv0, 0.0f)*inv0;
                float inv1 = 1.0f/(sqrtf(x1*x1+y1*y1+z1*z1)+EPSN);
                float mf1  = fminf((q[0][1]*x1+q[1][1]*y1+q[2][1]*z1)*inv1, 0.0f)*inv1;
                h3[0][0]=q[0][0]-mf0*x0; h3[1][0]=q[1][0]-mf0*y0; h3[2][0]=q[2][0]-mf0*z0;
                h3[0][1]=q[0][1]-mf1*x1; h3[1][1]=q[1][1]-mf1*y1; h3[2][1]=q[2][1]-mf1*z1;
            }
            #pragma unroll
            for (int d = 0; d < 3; d++){
                uint32_t hw = pk_hf(h3[d][0], h3[d][1]);
                uint32_t lw = pk_hf(h3[d][0]-hl(hw), h3[d][1]-hh(hw));
                *(uint32_t*)(sm + offd[d])       = hw;
                *(uint32_t*)(sm + IMG + offd[d]) = lw;
            }
        }
    }
}

// ---------------- main kernel ----------------
__global__ void __launch_bounds__(512, 2)
main_mma(const float* __restrict__ pf, const float* __restrict__ scale,
         const float* __restrict__ center, float* __restrict__ out)
{
    extern __shared__ char sm[];
    const uint32_t sb = smem_u32(sm);
    const uint32_t Ws = sb + WOFF;
    const int tid = threadIdx.x, w = tid >> 5, lane = tid & 31;
    const int b = blockIdx.y, m0 = blockIdx.x * TSP;
    const int mg = w >> 2, pq = w & 3;
    const int qr = lane >> 2, cb = (lane & 3)*2;

    {
        const char* src = (const char*)g_W16[0];
        #pragma unroll
        for (int t = 0; t < 4; t++){
            int i = tid + t*512;
            int o = i >> 4, kc = i & 15;
            cp16(sm + WOFF + (uint32_t)(o*256 + ((kc ^ (o&7)) << 4)), src + (size_t)i*16);
        }
        cpcommit();
    }

    // build hi/lo act images: row = channel c, col n = d*32+p, key (c>>1)&3
    #pragma unroll 1
    for (int it = 0; it < 6; it++){
        int idx = tid + it*512;
        int seg = idx & 7, d = (idx >> 3) % 3, c = idx / 24;
        float4 v = __ldg((const float4*)(pf + (((size_t)(b*128+c)*3+d)*NM + m0 + seg*4)));
        uint32_t off = (uint32_t)(c*ROWB + ((d*4 + ((seg>>1) ^ ((c>>1)&3))) << 4) + (seg&1)*8);
        uint2 hv = make_uint2(pk_hf(v.x, v.y), pk_hf(v.z, v.w));
        uint2 lv = make_uint2(pk_hf(v.x - hl(hv.x), v.y - hh(hv.x)),
                              pk_hf(v.z - hl(hv.y), v.w - hh(hv.y)));
        *(uint2*)(sm + off)       = hv;
        *(uint2*)(sm + IMG + off) = lv;
    }
    cpwait0();
    __syncthreads();

    float acc[2][3][4];
    const int bbase = b*128;

    #pragma unroll 1
    for (int l = 0; l < 4; l++){
        layer2p<2>(acc, Ws, sb, pq, mg*32, lane);
        __syncthreads();
        {
            const char* src = (const char*)g_W16[l+1];
            #pragma unroll
            for (int t = 0; t < 4; t++){
                int i = tid + t*512;
                int o = i >> 4, kc = i & 15;
                cp16(sm + WOFF + (uint32_t)(o*256 + ((kc ^ (o&7)) << 4)), src + (size_t)i*16);
            }
            cpcommit();
        }
        if      (l == 0) epi<0>(acc, sm, mg*32, pq, qr, cb, bbase);
        else if (l == 1) epi<1>(acc, sm, mg*32, pq, qr, cb, bbase);
        else if (l == 2) epi<2>(acc, sm, mg*32, pq, qr, cb, bbase);
        else             epi<1>(acc, sm, mg*32, pq, qr, cb, bbase);
        cpwait0();
        __syncthreads();
    }

    if (mg == 0){
        float facc[1][3][4];
        layer2p<1>(facc, Ws, sb, pq, 0, lane);
        if (lane < 8){
            const float sc = __ldg(scale + b);
            const int o2 = qr;
            #pragma unroll
            for (int d = 0; d < 3; d++){
                #pragma unroll
                for (int j = 0; j < 2; j++){
                    int p = pq*8 + cb + j;
                    float v = facc[0][d][j];
                    if (o2 == 0) v = v*sc + __ldg(center + b*3 + d);
                    out[((size_t)b*NM + m0 + p)*6 + o2*3 + d] = v;
                }
            }
        }
    }
}

// ---------------- fused setup: buildW (blk 0-39) | prep (40-47) | argmin (48-63) ----
__global__ void setup_k(const float* __restrict__ pc,
                        const float* __restrict__ z_pos, const float* __restrict__ z_dir,
                        const float* __restrict__ z_scalar, const float* __restrict__ gfeat,
                        const float* __restrict__ center, const float* __restrict__ scale,
                        const float* __restrict__ W1x, const float* __restrict__ W1xd,
                        const float* __restrict__ W1x_s, const float* __restrict__ W2x,
                        const float* __restrict__ W2xd, const float* __restrict__ W3x,
                        const float* __restrict__ W1g, const float* __restrict__ W1g_d,
                        const float* __restrict__ W1g_s, const float* __restrict__ W2g,
                        const float* __restrict__ W2g_d, const float* __restrict__ Wg_vs,
                        float* __restrict__ out)
{
    const int blk = blockIdx.x;
    const int tid = threadIdx.x;

    if (blk < 40){
        // ---- weight fp16 images ----
        const int m = blk >> 3, sub = blk & 7;
        #pragma unroll
        for (int t = 0; t < 8; t++){
            int i = sub*2048 + tid + t*256;
            int o = i >> 7, k = i & 127;
            float w = (m==0) ? W1x[o*136+k] : (m==1) ? W1xd[o*128+k] : (m==2) ? W2x[o*128+k]
                    : (m==3) ? W2xd[o*128+k] : ((o<2) ? W3x[o*128+k] : 0.0f);
            g_W16[m][i] = __float2half_rn(w);
        }
        return;
    }

    if (blk < 48){
        // ---- prep: warp-parallel matvecs; 8 warps x 16 outputs each ----
        __shared__ float vg[136*3], bq[128*3], bhm[128*3], nh[128], zs[8*3];
        const int b = blk - 40;
        const int wid = tid >> 5, lane = tid & 31;
        if (tid < 24){
            int r = tid/3, d = tid%3;
            zs[r*3+d] = (r < 2) ? (z_pos[(b*2+r)*3+d] - center[b*3+d]) / scale[b] : z_dir[(b*6+(r-2))*3+d];
        }
        __syncthreads();
        if (tid < 128){
            const int o = tid;
            g_s2v1[b*128+o] = W1x_s[o*2]*z_scalar[b*2] + W1x_s[o*2+1]*z_scalar[b*2+1];
            #pragma unroll
            for (int d = 0; d < 3; d++){
                float s = 0.0f;
                #pragma unroll
                for (int k = 0; k < 8; k++) s += W1x[o*136 + 128 + k] * zs[k*3+d];
                g_bias1[(b*128+o)*3+d] = s;
            }
        }
        for (int i = tid; i < 408; i += 256){
            int c = i/3, d = i%3;
            vg[i] = (c < 128) ? gfeat[(b*128+c)*3+d] : zs[(c-128)*3+d];
        }
        __syncthreads();

        // layer 1 (gate)
        #pragma unroll 1
        for (int oi = 0; oi < 16; oi++){
            const int o = wid*16 + oi;
            float s0=0.f, s1=0.f, s2=0.f;
            for (int c = lane; c < 136; c += 32){
                float wv = __ldg(W1g + o*136 + c);
                s0 += wv*vg[c*3]; s1 += wv*vg[c*3+1]; s2 += wv*vg[c*3+2];
            }
            wred3(s0, s1, s2);
            if (lane == 0){
                float sg = W1g_s[o*2]*z_scalar[b*2] + W1g_s[o*2+1]*z_scalar[b*2+1];
                float g = 1.0f + sg/(sqrtf(s0*s0+s1*s1+s2*s2)+EPSN);
                bq[o*3]=s0*g; bq[o*3+1]=s1*g; bq[o*3+2]=s2*g;
            }
        }
        __syncthreads();
        // layer 1d + LNA
        #pragma unroll 1
        for (int oi = 0; oi < 16; oi++){
            const int o = wid*16 + oi;
            float s0=0.f, s1=0.f, s2=0.f;
            for (int c = lane; c < 128; c += 32){
                float wv = __ldg(W1g_d + o*128 + c);
                s0 += wv*bq[c*3]; s1 += wv*bq[c*3+1]; s2 += wv*bq[c*3+2];
            }
            wred3(s0, s1, s2);
            if (lane == 0){
                float q0=bq[o*3], q1=bq[o*3+1], q2=bq[o*3+2];
                float inv = 1.0f/(sqrtf(s0*s0+s1*s1+s2*s2)+EPSN);
                float mf = fminf((q0*s0+q1*s1+q2*s2)*inv, 0.0f)*inv;
                bhm[o*3]=q0-mf*s0; bhm[o*3+1]=q1-mf*s1; bhm[o*3+2]=q2-mf*s2;
            }
        }
        __syncthreads();
        // layer 2
        #pragma unroll 1
        for (int oi = 0; oi < 16; oi++){
            const int o = wid*16 + oi;
            float s0=0.f, s1=0.f, s2=0.f;
            for (int c = lane; c < 128; c += 32){
                float wv = __ldg(W2g + o*128 + c);
                s0 += wv*bhm[c*3]; s1 += wv*bhm[c*3+1]; s2 += wv*bhm[c*3+2];
            }
            wred3(s0, s1, s2);
            if (lane == 0){ bq[o*3]=s0; bq[o*3+1]=s1; bq[o*3+2]=s2; }
        }
        __syncthreads();
        // layer 2d + LNA + norm
        #pragma unroll 1
        for (int oi = 0; oi < 16; oi++){
            const int o = wid*16 + oi;
            float s0=0.f, s1=0.f, s2=0.f;
            for (int c = lane; c < 128; c += 32){
                float wv = __ldg(W2g_d + o*128 + c);
                s0 += wv*bq[c*3]; s1 += wv*bq[c*3+1]; s2 += wv*bq[c*3+2];
            }
            wred3(s0, s1, s2);
            if (lane == 0){
                float q0=bq[o*3], q1=bq[o*3+1], q2=bq[o*3+2];
                float inv = 1.0f/(sqrtf(s0*s0+s1*s1+s2*s2)+EPSN);
                float mf = fminf((q0*s0+q1*s1+q2*s2)*inv, 0.0f)*inv;
                float h0=q0-mf*s0, h1=q1-mf*s1, h2=q2-mf*s2;
                nh[o] = sqrtf(h0*h0+h1*h1+h2*h2);
            }
        }
        __syncthreads();
        // gripper (warps 0,1)
        if (wid < 2){
            const int o = wid;
            float s = 0.0f;
            for (int c = lane; c < 128; c += 32) s += __ldg(Wg_vs + o*128 + c) * nh[c];
            #pragma unroll
            for (int t = 16; t; t >>= 1) s += __shfl_xor_sync(0xFFFFFFFFu, s, t);
            if (lane == 0){
                float gr = 1.0f/(1.0f+expf(-s));
                g_grip[b*2+o] = gr;
                out[GRIP_OFF + b*2+o] = gr;
            }
        }
        return;
    }

    // ---- argmin (blocks 48-63) ----
    {
        __shared__ float sv[256]; __shared__ int si[256];
        const int be = blk - 48, b = be >> 1;
        const float inv = 1.0f / scale[b];
        const float zx = (z_pos[be*3+0] - center[b*3+0]) * inv;
        const float zy = (z_pos[be*3+1] - center[b*3+1]) * inv;
        const float zz = (z_pos[be*3+2] - center[b*3+2]) * inv;
        const float* p = pc + (size_t)b*NM*3;
        float best = 3.4e38f; int bi = 0;
        #pragma unroll 4
        for (int m = tid; m < NM; m += 256){
            float dx=zx-p[m*3], dy=zy-p[m*3+1], dz=zz-p[m*3+2];
            float d = sqrtf(dx*dx+dy*dy+dz*dz);
            if (d < best){ best = d; bi = m; }
        }
        sv[tid]=best; si[tid]=bi;
        __syncthreads();
        for (int s = 128; s > 0; s >>= 1){
            if (tid < s){
                float ov = sv[tid+s]; int oi = si[tid+s];
                if (ov < sv[tid] || (ov == sv[tid] && oi < si[tid])){
                    sv[tid]=ov; si[tid]=oi;
                }
            }
            __syncthreads();
        }
        if (tid == 0) g_closest[be] = si[0];
    }
}

__global__ void assemble_k(float* __restrict__ out)
{
    const int t = threadIdx.x;
    if (t < 112){
        int b = t/14, j = t%14, e = j/7, r = j%7;
        float v;
        if (r == 0) v = g_grip[b*2+e];
        else { int m = g_closest[b*2+e]; v = out[((size_t)b*NM+m)*6 + (r-1)]; }
        out[AC_OFF + t] = v;
    }
}

// ---------------- launch ----------------
extern "C" void kernel_launch(void* const* d_in, const int* in_sizes, int n_in,
                              void* d_out, int out_size)
{
    const float* pc        = (const float*)d_in[0];
    const float* z_pos     = (const float*)d_in[1];
    const float* z_dir     = (const float*)d_in[2];
    const float* z_scalar  = (const float*)d_in[3];
    const float* point_feat= (const float*)d_in[4];
    const float* gfeat     = (const float*)d_in[5];
    const float* center    = (const float*)d_in[6];
    const float* scale     = (const float*)d_in[7];
    const float* W1x       = (const float*)d_in[8];
    const float* W1x_d     = (const float*)d_in[9];
    const float* W1x_s     = (const float*)d_in[10];
    const float* W2x       = (const float*)d_in[11];
    const float* W2x_d     = (const float*)d_in[12];
    const float* W3x       = (const float*)d_in[13];
    const float* W1g       = (const float*)d_in[14];
    const float* W1g_d     = (const float*)d_in[15];
    const float* W1g_s     = (const float*)d_in[16];
    const float* W2g       = (const float*)d_in[17];
    const float* W2g_d     = (const float*)d_in[18];
    const float* Wg_vs     = (const float*)d_in[19];
    float* out = (float*)d_out;

    cudaFuncSetAttribute(main_mma, cudaFuncAttributeMaxDynamicSharedMemorySize, SMEM_TOTAL);

    setup_k<<<64, 256>>>(pc, z_pos, z_dir, z_scalar, gfeat, center, scale,
                         W1x, W1x_d, W1x_s, W2x, W2x_d, W3x,
                         W1g, W1g_d, W1g_s, W2g, W2g_d, Wg_vs, out);
    main_mma<<<dim3(NM/TSP, NB), 512, SMEM_TOTAL>>>(point_feat, scale, center, out);
    assemble_k<<<1, 128>>>(out);
}